// round 7
// baseline (speedup 1.0000x reference)
#include <cuda_runtime.h>
#include <cuda_bf16.h>
#include <math.h>
#include <stdint.h>

#define BATCH 8
#define SEQ 1024
#define DMODEL 768
#define NH 12
#define HD 64
#define ATTN_SCALE 0.125f
#define MTOT (BATCH * SEQ)         /* 8192 */
#define NQKV (3 * DMODEL)          /* 2304 */

#define QT_STRIDE 132
#define KV_STRIDE 68

typedef __nv_bfloat16 bf16;

// ---------------------------------------------------------------------------
// Scratch — EXACTLY the R2 set (100.7 MB fp32, known-good module layout)
// ---------------------------------------------------------------------------
__device__ float g_q[BATCH * NH * SEQ * HD];
__device__ float g_k[BATCH * NH * SEQ * HD];
__device__ float g_v[BATCH * NH * SEQ * HD];
__device__ float g_ctx[BATCH * NH * SEQ * HD];

// ---------------------------------------------------------------------------
// HMMA helper (m16n8k16, bf16 in / fp32 accumulate)
// ---------------------------------------------------------------------------
__device__ __forceinline__ void mma16816(float* c, const uint32_t* a,
                                         const uint32_t* b) {
    asm volatile(
        "mma.sync.aligned.m16n8k16.row.col.f32.bf16.bf16.f32 "
        "{%0,%1,%2,%3}, {%4,%5,%6,%7}, {%8,%9}, {%0,%1,%2,%3};"
        : "+f"(c[0]), "+f"(c[1]), "+f"(c[2]), "+f"(c[3])
        : "r"(a[0]), "r"(a[1]), "r"(a[2]), "r"(a[3]), "r"(b[0]), "r"(b[1]));
}

// ---------------------------------------------------------------------------
// QKV GEMM via HMMA with in-kernel hi/lo split.
// C[128m x 128n] = A[8192x768] @ W[768x2304] + bias, scattered into q/k/v.
// A staged as [m][k] bf16 (hi/lo), W staged TRANSPOSED as [n][k] bf16 (hi/lo),
// stride 40 elems. BK=32. 256 threads / 8 warps: warp (wid&3)->32 rows,
// (wid>>2)->64 cols. 3-term split: AhWh + AhWl + AlWh.
// ---------------------------------------------------------------------------
__global__ __launch_bounds__(256) void qkv_gemm_hmma(
    const float* __restrict__ A, const float* __restrict__ W,
    const float* __restrict__ bias)
{
    __shared__ bf16 smem[512 * 40];          // 40960 B static
    bf16* sAh = smem;
    bf16* sAl = smem + 128 * 40;
    bf16* sBh = smem + 256 * 40;
    bf16* sBl = smem + 384 * 40;

    const int tid = threadIdx.x;
    const int wid = tid >> 5, lane = tid & 31;
    const int nb = blockIdx.x * 128, mb = blockIdx.y * 128;
    const int wrow = (wid & 3) * 32;
    const int wcol = (wid >> 2) * 64;
    const int g = lane >> 2, tig = lane & 3;

    float acc[2][8][4];
#pragma unroll
    for (int mi = 0; mi < 2; ++mi)
#pragma unroll
        for (int ni = 0; ni < 8; ++ni)
#pragma unroll
            for (int r = 0; r < 4; ++r) acc[mi][ni][r] = 0.f;

    for (int kt = 0; kt < DMODEL; kt += 32) {
        // --- Stage A tile [128 m][32 k]: float4 load, split, store hi/lo ---
#pragma unroll
        for (int it = 0; it < 4; ++it) {
            int id = it * 256 + tid;           // 0..1023
            int row = id >> 3, c = id & 7;     // col = c*4
            float4 v = *reinterpret_cast<const float4*>(
                &A[(size_t)(mb + row) * DMODEL + kt + c * 4]);
            bf16 h0 = __float2bfloat16(v.x), h1 = __float2bfloat16(v.y);
            bf16 h2 = __float2bfloat16(v.z), h3 = __float2bfloat16(v.w);
            bf16 l0 = __float2bfloat16(v.x - __bfloat162float(h0));
            bf16 l1 = __float2bfloat16(v.y - __bfloat162float(h1));
            bf16 l2 = __float2bfloat16(v.z - __bfloat162float(h2));
            bf16 l3 = __float2bfloat16(v.w - __bfloat162float(h3));
            int o = row * 40 + c * 4;
            sAh[o + 0] = h0; sAh[o + 1] = h1; sAh[o + 2] = h2; sAh[o + 3] = h3;
            sAl[o + 0] = l0; sAl[o + 1] = l1; sAl[o + 2] = l2; sAl[o + 3] = l3;
        }
        // --- Stage W tile [32 k][128 n] TRANSPOSED -> sB[n][k] hi/lo ---
#pragma unroll
        for (int it = 0; it < 4; ++it) {
            int id = it * 256 + tid;           // 0..1023
            int k = id >> 5, c = id & 31;      // n = c*4
            float4 v = *reinterpret_cast<const float4*>(
                &W[(size_t)(kt + k) * NQKV + nb + c * 4]);
            bf16 h0 = __float2bfloat16(v.x), h1 = __float2bfloat16(v.y);
            bf16 h2 = __float2bfloat16(v.z), h3 = __float2bfloat16(v.w);
            int n = c * 4;
            sBh[(n + 0) * 40 + k] = h0;
            sBh[(n + 1) * 40 + k] = h1;
            sBh[(n + 2) * 40 + k] = h2;
            sBh[(n + 3) * 40 + k] = h3;
            sBl[(n + 0) * 40 + k] = __float2bfloat16(v.x - __bfloat162float(h0));
            sBl[(n + 1) * 40 + k] = __float2bfloat16(v.y - __bfloat162float(h1));
            sBl[(n + 2) * 40 + k] = __float2bfloat16(v.z - __bfloat162float(h2));
            sBl[(n + 3) * 40 + k] = __float2bfloat16(v.w - __bfloat162float(h3));
        }
        __syncthreads();

#pragma unroll
        for (int ks = 0; ks < 2; ++ks) {
            const int ko = ks * 16;
            uint32_t ah[2][4], al[2][4];
#pragma unroll
            for (int mi = 0; mi < 2; ++mi) {
                const bf16* p = sAh + (wrow + mi * 16 + g) * 40 + ko + 2 * tig;
                ah[mi][0] = *reinterpret_cast<const uint32_t*>(p);
                ah[mi][1] = *reinterpret_cast<const uint32_t*>(p + 8 * 40);
                ah[mi][2] = *reinterpret_cast<const uint32_t*>(p + 8);
                ah[mi][3] = *reinterpret_cast<const uint32_t*>(p + 8 * 40 + 8);
                const bf16* q = sAl + (wrow + mi * 16 + g) * 40 + ko + 2 * tig;
                al[mi][0] = *reinterpret_cast<const uint32_t*>(q);
                al[mi][1] = *reinterpret_cast<const uint32_t*>(q + 8 * 40);
                al[mi][2] = *reinterpret_cast<const uint32_t*>(q + 8);
                al[mi][3] = *reinterpret_cast<const uint32_t*>(q + 8 * 40 + 8);
            }
            uint32_t bhf[8][2], blf[8][2];
#pragma unroll
            for (int ni = 0; ni < 8; ++ni) {
                const bf16* p = sBh + (wcol + ni * 8 + g) * 40 + ko + 2 * tig;
                bhf[ni][0] = *reinterpret_cast<const uint32_t*>(p);
                bhf[ni][1] = *reinterpret_cast<const uint32_t*>(p + 8);
                const bf16* q = sBl + (wcol + ni * 8 + g) * 40 + ko + 2 * tig;
                blf[ni][0] = *reinterpret_cast<const uint32_t*>(q);
                blf[ni][1] = *reinterpret_cast<const uint32_t*>(q + 8);
            }
#pragma unroll
            for (int mi = 0; mi < 2; ++mi)
#pragma unroll
                for (int ni = 0; ni < 8; ++ni) {
                    mma16816(acc[mi][ni], ah[mi], bhf[ni]);
                    mma16816(acc[mi][ni], ah[mi], blf[ni]);
                    mma16816(acc[mi][ni], al[mi], bhf[ni]);
                }
        }
        __syncthreads();
    }

    // Epilogue: scatter fp32 into g_q/g_k/g_v [B,H,S,HD] + bias
#pragma unroll
    for (int mi = 0; mi < 2; ++mi)
#pragma unroll
        for (int ni = 0; ni < 8; ++ni) {
            int col = nb + wcol + ni * 8 + 2 * tig;
            int which = col / DMODEL;
            int rem = col - which * DMODEL;
            int h = rem >> 6, d = rem & 63;
            float* dst = (which == 0) ? g_q : ((which == 1) ? g_k : g_v);
            float b0 = bias[col], b1 = bias[col + 1];
#pragma unroll
            for (int half = 0; half < 2; ++half) {
                int m = mb + wrow + mi * 16 + g + half * 8;
                int bb = m >> 10, s = m & 1023;
                float2 o = make_float2(acc[mi][ni][half * 2 + 0] + b0,
                                       acc[mi][ni][half * 2 + 1] + b1);
                *reinterpret_cast<float2*>(
                    &dst[(((size_t)(bb * NH + h) * SEQ + s) * HD) + d]) = o;
            }
        }
}

// ---------------------------------------------------------------------------
// Flash attention (byte-identical to R2 passing kernel)
// ---------------------------------------------------------------------------
__global__ __launch_bounds__(128) void attn_kernel()
{
    extern __shared__ float sm[];
    float* Qt = sm;
    float* KV = Qt + 64 * QT_STRIDE;
    float* Pt = KV + 64 * KV_STRIDE;
    float* alpha_s = Pt + 64 * 128;
    float* linv = alpha_s + 128;

    const int tid = threadIdx.x;
    const int qb = blockIdx.x * 128;
    const int h = blockIdx.y, b = blockIdx.z;
    const size_t base = ((size_t)(b * NH + h)) * SEQ * HD;
    const float* Qg = g_q + base;
    const float* Kg = g_k + base;
    const float* Vg = g_v + base;

    const int warp = tid >> 5, lane = tid & 31;
    const int lm = lane & 3, ln = lane >> 2;
    const int i0 = warp * 32 + lm * 8;
    const int j0 = ln * 8;

#pragma unroll
    for (int it = 0; it < 16; ++it) {
        int g = it * 128 + tid;
        int i = g >> 4, d4 = (g & 15) << 2;
        float4 v = *reinterpret_cast<const float4*>(&Qg[(size_t)(qb + i) * HD + d4]);
        Qt[(d4 + 0) * QT_STRIDE + i] = v.x;
        Qt[(d4 + 1) * QT_STRIDE + i] = v.y;
        Qt[(d4 + 2) * QT_STRIDE + i] = v.z;
        Qt[(d4 + 3) * QT_STRIDE + i] = v.w;
    }

    float oacc[8][8];
#pragma unroll
    for (int r = 0; r < 8; ++r)
#pragma unroll
        for (int c = 0; c < 8; ++c) oacc[r][c] = 0.f;
    float m_run = -1e30f, l_run = 0.f;

    for (int kt = 0; kt < SEQ; kt += 64) {
#pragma unroll
        for (int it = 0; it < 8; ++it) {
            int g = it * 128 + tid;
            int j = g >> 4, d4 = (g & 15) << 2;
            float4 v = *reinterpret_cast<const float4*>(&Kg[(size_t)(kt + j) * HD + d4]);
            KV[(d4 + 0) * KV_STRIDE + j] = v.x;
            KV[(d4 + 1) * KV_STRIDE + j] = v.y;
            KV[(d4 + 2) * KV_STRIDE + j] = v.z;
            KV[(d4 + 3) * KV_STRIDE + j] = v.w;
        }
        __syncthreads();

        float sacc[8][8];
#pragma unroll
        for (int r = 0; r < 8; ++r)
#pragma unroll
            for (int c = 0; c < 8; ++c) sacc[r][c] = 0.f;
#pragma unroll
        for (int d = 0; d < 64; ++d) {
            float qa[8], kb[8];
            *reinterpret_cast<float4*>(&qa[0]) =
                *reinterpret_cast<const float4*>(&Qt[d * QT_STRIDE + i0]);
            *reinterpret_cast<float4*>(&qa[4]) =
                *reinterpret_cast<const float4*>(&Qt[d * QT_STRIDE + i0 + 4]);
            *reinterpret_cast<float4*>(&kb[0]) =
                *reinterpret_cast<const float4*>(&KV[d * KV_STRIDE + j0]);
            *reinterpret_cast<float4*>(&kb[4]) =
                *reinterpret_cast<const float4*>(&KV[d * KV_STRIDE + j0 + 4]);
#pragma unroll
            for (int r = 0; r < 8; ++r)
#pragma unroll
                for (int c = 0; c < 8; ++c)
                    sacc[r][c] = fmaf(qa[r], kb[c], sacc[r][c]);
        }
#pragma unroll
        for (int c = 0; c < 8; ++c) {
            *reinterpret_cast<float4*>(&Pt[(j0 + c) * 128 + i0]) =
                make_float4(sacc[0][c], sacc[1][c], sacc[2][c], sacc[3][c]);
            *reinterpret_cast<float4*>(&Pt[(j0 + c) * 128 + i0 + 4]) =
                make_float4(sacc[4][c], sacc[5][c], sacc[6][c], sacc[7][c]);
        }
        __syncthreads();

#pragma unroll
        for (int it = 0; it < 8; ++it) {
            int g = it * 128 + tid;
            int j = g >> 4, d4 = (g & 15) << 2;
            *reinterpret_cast<float4*>(&KV[j * KV_STRIDE + d4]) =
                *reinterpret_cast<const float4*>(&Vg[(size_t)(kt + j) * HD + d4]);
        }

        {
            float tmax = -1e30f;
#pragma unroll 16
            for (int j = 0; j < 64; ++j)
                tmax = fmaxf(tmax, Pt[j * 128 + tid]);
            float m_new = fmaxf(m_run, tmax * ATTN_SCALE);
            float a = __expf(m_run - m_new);
            float sum = 0.f;
#pragma unroll 16
            for (int j = 0; j < 64; ++j) {
                float p = __expf(fmaf(Pt[j * 128 + tid], ATTN_SCALE, -m_new));
                Pt[j * 128 + tid] = p;
                sum += p;
            }
            l_run = fmaf(l_run, a, sum);
            m_run = m_new;
            alpha_s[tid] = a;
        }
        __syncthreads();

#pragma unroll
        for (int r = 0; r < 8; ++r) {
            float a = alpha_s[i0 + r];
#pragma unroll
            for (int c = 0; c < 8; ++c) oacc[r][c] *= a;
        }
#pragma unroll
        for (int j = 0; j < 64; ++j) {
            float p[8], vv[8];
            *reinterpret_cast<float4*>(&p[0]) =
                *reinterpret_cast<const float4*>(&Pt[j * 128 + i0]);
            *reinterpret_cast<float4*>(&p[4]) =
                *reinterpret_cast<const float4*>(&Pt[j * 128 + i0 + 4]);
            *reinterpret_cast<float4*>(&vv[0]) =
                *reinterpret_cast<const float4*>(&KV[j * KV_STRIDE + j0]);
            *reinterpret_cast<float4*>(&vv[4]) =
                *reinterpret_cast<const float4*>(&KV[j * KV_STRIDE + j0 + 4]);
#pragma unroll
            for (int r = 0; r < 8; ++r)
#pragma unroll
                for (int c = 0; c < 8; ++c)
                    oacc[r][c] = fmaf(p[r], vv[c], oacc[r][c]);
        }
        __syncthreads();
    }

    linv[tid] = 1.f / l_run;
    __syncthreads();

    float* Og = g_ctx + base;
#pragma unroll
    for (int r = 0; r < 8; ++r) {
        int i = i0 + r;
        float inv = linv[i];
        *reinterpret_cast<float4*>(&Og[(size_t)(qb + i) * HD + j0]) =
            make_float4(oacc[r][0] * inv, oacc[r][1] * inv,
                        oacc[r][2] * inv, oacc[r][3] * inv);
        *reinterpret_cast<float4*>(&Og[(size_t)(qb + i) * HD + j0 + 4]) =
            make_float4(oacc[r][4] * inv, oacc[r][5] * inv,
                        oacc[r][6] * inv, oacc[r][7] * inv);
    }
}

// ---------------------------------------------------------------------------
// Proj GEMM (byte-identical to R2 passing kernel)
// ---------------------------------------------------------------------------
__global__ __launch_bounds__(256) void proj_gemm_kernel(
    const float* __restrict__ W, const float* __restrict__ bias,
    float* __restrict__ out)
{
    __shared__ float Ats[16 * 128];
    __shared__ float Bs[16 * 128];

    const int tid = threadIdx.x;
    const int nb = blockIdx.x * 128;
    const int mb = blockIdx.y * 128;

    const int warp = tid >> 5, lane = tid & 31;
    const int wm = warp & 3, wn = warp >> 2;
    const int lm = lane & 3, ln = lane >> 2;
    const int ri = wm * 32 + lm * 8;
    const int cj = wn * 64 + ln * 8;

    float acc[8][8];
#pragma unroll
    for (int r = 0; r < 8; ++r)
#pragma unroll
        for (int c = 0; c < 8; ++c) acc[r][c] = 0.f;

    for (int kt = 0; kt < DMODEL; kt += 16) {
        const int hk = kt >> 6;
        const int dk = kt & 63;
#pragma unroll
        for (int it = 0; it < 2; ++it) {
            int g = it * 256 + tid;
            int row = g >> 2, k4 = (g & 3) << 2;
            int m = mb + row;
            int b = m >> 10, s = m & 1023;
            float4 v = *reinterpret_cast<const float4*>(
                &g_ctx[(((size_t)(b * NH + hk) * SEQ + s) * HD) + dk + k4]);
            Ats[(k4 + 0) * 128 + row] = v.x;
            Ats[(k4 + 1) * 128 + row] = v.y;
            Ats[(k4 + 2) * 128 + row] = v.z;
            Ats[(k4 + 3) * 128 + row] = v.w;
        }
#pragma unroll
        for (int it = 0; it < 2; ++it) {
            int g = it * 256 + tid;
            int k = g >> 5, n4 = (g & 31) << 2;
            *reinterpret_cast<float4*>(&Bs[k * 128 + n4]) =
                *reinterpret_cast<const float4*>(
                    &W[(size_t)(kt + k) * DMODEL + nb + n4]);
        }
        __syncthreads();
#pragma unroll
        for (int k = 0; k < 16; ++k) {
            float a[8], b[8];
            *reinterpret_cast<float4*>(&a[0]) =
                *reinterpret_cast<const float4*>(&Ats[k * 128 + ri]);
            *reinterpret_cast<float4*>(&a[4]) =
                *reinterpret_cast<const float4*>(&Ats[k * 128 + ri + 4]);
            *reinterpret_cast<float4*>(&b[0]) =
                *reinterpret_cast<const float4*>(&Bs[k * 128 + cj]);
            *reinterpret_cast<float4*>(&b[4]) =
                *reinterpret_cast<const float4*>(&Bs[k * 128 + cj + 4]);
#pragma unroll
            for (int r = 0; r < 8; ++r)
#pragma unroll
                for (int c = 0; c < 8; ++c)
                    acc[r][c] = fmaf(a[r], b[c], acc[r][c]);
        }
        __syncthreads();
    }

    float bb[8];
#pragma unroll
    for (int c = 0; c < 8; ++c) bb[c] = bias[nb + cj + c];
#pragma unroll
    for (int r = 0; r < 8; ++r) {
        int m = mb + ri + r;
        float* p = out + (size_t)m * DMODEL + nb + cj;
        *reinterpret_cast<float4*>(p) = make_float4(
            acc[r][0] + bb[0], acc[r][1] + bb[1],
            acc[r][2] + bb[2], acc[r][3] + bb[3]);
        *reinterpret_cast<float4*>(p + 4) = make_float4(
            acc[r][4] + bb[4], acc[r][5] + bb[5],
            acc[r][6] + bb[6], acc[r][7] + bb[7]);
    }
}

// ---------------------------------------------------------------------------
extern "C" void kernel_launch(void* const* d_in, const int* in_sizes, int n_in,
                              void* d_out, int out_size)
{
    const float* hidden = (const float*)d_in[0];
    const float* w_qkv  = (const float*)d_in[1];
    const float* b_qkv  = (const float*)d_in[2];
    const float* w_proj = (const float*)d_in[3];
    const float* b_proj = (const float*)d_in[4];
    float* out = (float*)d_out;

    const size_t attn_smem =
        (size_t)(64 * QT_STRIDE + 64 * KV_STRIDE + 64 * 128 + 256) * sizeof(float);
    cudaFuncSetAttribute(attn_kernel,
                         cudaFuncAttributeMaxDynamicSharedMemorySize,
                         (int)attn_smem);

    qkv_gemm_hmma<<<dim3(NQKV / 128, MTOT / 128), 256>>>(hidden, w_qkv, b_qkv);
    attn_kernel<<<dim3(SEQ / 128, NH, BATCH), 128, attn_smem>>>();
    proj_gemm_kernel<<<dim3(DMODEL / 128, MTOT / 128), 256>>>(
        w_proj, b_proj, out);
}

// round 9
// speedup vs baseline: 1.5545x; 1.5545x over previous
#include <cuda_runtime.h>
#include <cuda_bf16.h>
#include <math.h>
#include <stdint.h>

#define BATCH 8
#define SEQ 1024
#define DMODEL 768
#define NH 12
#define HD 64
#define ATTN_SCALE 0.125f
#define MTOT (BATCH * SEQ)         /* 8192 */
#define NQKV (3 * DMODEL)          /* 2304 */

typedef __nv_bfloat16 bf16;

// ---------------------------------------------------------------------------
// Scratch — same fp32 set as passing R2/R7 (100.7 MB)
// ---------------------------------------------------------------------------
__device__ float g_q[BATCH * NH * SEQ * HD];
__device__ float g_k[BATCH * NH * SEQ * HD];
__device__ float g_v[BATCH * NH * SEQ * HD];
__device__ float g_ctx[BATCH * NH * SEQ * HD];

// ---------------------------------------------------------------------------
// HMMA helper (m16n8k16, bf16 in / fp32 accumulate)
// ---------------------------------------------------------------------------
__device__ __forceinline__ void mma16816(float* c, const uint32_t* a,
                                         const uint32_t* b) {
    asm volatile(
        "mma.sync.aligned.m16n8k16.row.col.f32.bf16.bf16.f32 "
        "{%0,%1,%2,%3}, {%4,%5,%6,%7}, {%8,%9}, {%0,%1,%2,%3};"
        : "+f"(c[0]), "+f"(c[1]), "+f"(c[2]), "+f"(c[3])
        : "r"(a[0]), "r"(a[1]), "r"(a[2]), "r"(a[3]), "r"(b[0]), "r"(b[1]));
}

__device__ __forceinline__ void split2(float v0, float v1,
                                       __nv_bfloat162& h, __nv_bfloat162& l) {
    bf16 h0 = __float2bfloat16(v0), h1 = __float2bfloat16(v1);
    h = __halves2bfloat162(h0, h1);
    l = __halves2bfloat162(__float2bfloat16(v0 - __bfloat162float(h0)),
                           __float2bfloat16(v1 - __bfloat162float(h1)));
}

// ---------------------------------------------------------------------------
// QKV GEMM via HMMA (byte-identical to passing R7 kernel)
// ---------------------------------------------------------------------------
__global__ __launch_bounds__(256) void qkv_gemm_hmma(
    const float* __restrict__ A, const float* __restrict__ W,
    const float* __restrict__ bias)
{
    __shared__ bf16 smem[512 * 40];
    bf16* sAh = smem;
    bf16* sAl = smem + 128 * 40;
    bf16* sBh = smem + 256 * 40;
    bf16* sBl = smem + 384 * 40;

    const int tid = threadIdx.x;
    const int wid = tid >> 5, lane = tid & 31;
    const int nb = blockIdx.x * 128, mb = blockIdx.y * 128;
    const int wrow = (wid & 3) * 32;
    const int wcol = (wid >> 2) * 64;
    const int g = lane >> 2, tig = lane & 3;

    float acc[2][8][4];
#pragma unroll
    for (int mi = 0; mi < 2; ++mi)
#pragma unroll
        for (int ni = 0; ni < 8; ++ni)
#pragma unroll
            for (int r = 0; r < 4; ++r) acc[mi][ni][r] = 0.f;

    for (int kt = 0; kt < DMODEL; kt += 32) {
#pragma unroll
        for (int it = 0; it < 4; ++it) {
            int id = it * 256 + tid;
            int row = id >> 3, c = id & 7;
            float4 v = *reinterpret_cast<const float4*>(
                &A[(size_t)(mb + row) * DMODEL + kt + c * 4]);
            bf16 h0 = __float2bfloat16(v.x), h1 = __float2bfloat16(v.y);
            bf16 h2 = __float2bfloat16(v.z), h3 = __float2bfloat16(v.w);
            bf16 l0 = __float2bfloat16(v.x - __bfloat162float(h0));
            bf16 l1 = __float2bfloat16(v.y - __bfloat162float(h1));
            bf16 l2 = __float2bfloat16(v.z - __bfloat162float(h2));
            bf16 l3 = __float2bfloat16(v.w - __bfloat162float(h3));
            int o = row * 40 + c * 4;
            sAh[o + 0] = h0; sAh[o + 1] = h1; sAh[o + 2] = h2; sAh[o + 3] = h3;
            sAl[o + 0] = l0; sAl[o + 1] = l1; sAl[o + 2] = l2; sAl[o + 3] = l3;
        }
#pragma unroll
        for (int it = 0; it < 4; ++it) {
            int id = it * 256 + tid;
            int k = id >> 5, c = id & 31;
            float4 v = *reinterpret_cast<const float4*>(
                &W[(size_t)(kt + k) * NQKV + nb + c * 4]);
            bf16 h0 = __float2bfloat16(v.x), h1 = __float2bfloat16(v.y);
            bf16 h2 = __float2bfloat16(v.z), h3 = __float2bfloat16(v.w);
            int n = c * 4;
            sBh[(n + 0) * 40 + k] = h0;
            sBh[(n + 1) * 40 + k] = h1;
            sBh[(n + 2) * 40 + k] = h2;
            sBh[(n + 3) * 40 + k] = h3;
            sBl[(n + 0) * 40 + k] = __float2bfloat16(v.x - __bfloat162float(h0));
            sBl[(n + 1) * 40 + k] = __float2bfloat16(v.y - __bfloat162float(h1));
            sBl[(n + 2) * 40 + k] = __float2bfloat16(v.z - __bfloat162float(h2));
            sBl[(n + 3) * 40 + k] = __float2bfloat16(v.w - __bfloat162float(h3));
        }
        __syncthreads();

#pragma unroll
        for (int ks = 0; ks < 2; ++ks) {
            const int ko = ks * 16;
            uint32_t ah[2][4], al[2][4];
#pragma unroll
            for (int mi = 0; mi < 2; ++mi) {
                const bf16* p = sAh + (wrow + mi * 16 + g) * 40 + ko + 2 * tig;
                ah[mi][0] = *reinterpret_cast<const uint32_t*>(p);
                ah[mi][1] = *reinterpret_cast<const uint32_t*>(p + 8 * 40);
                ah[mi][2] = *reinterpret_cast<const uint32_t*>(p + 8);
                ah[mi][3] = *reinterpret_cast<const uint32_t*>(p + 8 * 40 + 8);
                const bf16* q = sAl + (wrow + mi * 16 + g) * 40 + ko + 2 * tig;
                al[mi][0] = *reinterpret_cast<const uint32_t*>(q);
                al[mi][1] = *reinterpret_cast<const uint32_t*>(q + 8 * 40);
                al[mi][2] = *reinterpret_cast<const uint32_t*>(q + 8);
                al[mi][3] = *reinterpret_cast<const uint32_t*>(q + 8 * 40 + 8);
            }
            uint32_t bhf[8][2], blf[8][2];
#pragma unroll
            for (int ni = 0; ni < 8; ++ni) {
                const bf16* p = sBh + (wcol + ni * 8 + g) * 40 + ko + 2 * tig;
                bhf[ni][0] = *reinterpret_cast<const uint32_t*>(p);
                bhf[ni][1] = *reinterpret_cast<const uint32_t*>(p + 8);
                const bf16* q = sBl + (wcol + ni * 8 + g) * 40 + ko + 2 * tig;
                blf[ni][0] = *reinterpret_cast<const uint32_t*>(q);
                blf[ni][1] = *reinterpret_cast<const uint32_t*>(q + 8);
            }
#pragma unroll
            for (int mi = 0; mi < 2; ++mi)
#pragma unroll
                for (int ni = 0; ni < 8; ++ni) {
                    mma16816(acc[mi][ni], ah[mi], bhf[ni]);
                    mma16816(acc[mi][ni], ah[mi], blf[ni]);
                    mma16816(acc[mi][ni], al[mi], bhf[ni]);
                }
        }
        __syncthreads();
    }

#pragma unroll
    for (int mi = 0; mi < 2; ++mi)
#pragma unroll
        for (int ni = 0; ni < 8; ++ni) {
            int col = nb + wcol + ni * 8 + 2 * tig;
            int which = col / DMODEL;
            int rem = col - which * DMODEL;
            int h = rem >> 6, d = rem & 63;
            float* dst = (which == 0) ? g_q : ((which == 1) ? g_k : g_v);
            float b0 = bias[col], b1 = bias[col + 1];
#pragma unroll
            for (int half = 0; half < 2; ++half) {
                int m = mb + wrow + mi * 16 + g + half * 8;
                int bb = m >> 10, s = m & 1023;
                float2 o = make_float2(acc[mi][ni][half * 2 + 0] + b0,
                                       acc[mi][ni][half * 2 + 1] + b1);
                *reinterpret_cast<float2*>(
                    &dst[(((size_t)(bb * NH + h) * SEQ + s) * HD) + d]) = o;
            }
        }
}

// ---------------------------------------------------------------------------
// Flash attention via HMMA (bf16 hi/lo, 3-term).  256 thr / 8 warps.
// CTA: one (b,h), 128 q rows. kv tiles of 64.
// Warp (wid&3) -> 32 q rows; (wid>>2) -> 32-col half of the 64-wide tile.
// smem offsets (bytes):
//   sQh 0 [128*72 bf16], sQl 18432, sKVh 36864 [64*72], sKVl 46080,
//   sPt 55296 [64*132 f32], sPh 89088 [128*36 u32], sPl 107520,
//   sAlpha 125952 [128 f32], sLinv 126464. total 126976.
// ---------------------------------------------------------------------------
#define ATTN_SMEM 126976

__global__ __launch_bounds__(256) void attn_hmma()
{
    extern __shared__ char sm[];
    bf16* sQh = (bf16*)(sm + 0);
    bf16* sQl = (bf16*)(sm + 18432);
    bf16* sKVh = (bf16*)(sm + 36864);
    bf16* sKVl = (bf16*)(sm + 46080);
    float* sPt = (float*)(sm + 55296);
    uint32_t* sPh = (uint32_t*)(sm + 89088);
    uint32_t* sPl = (uint32_t*)(sm + 107520);
    float* sAlpha = (float*)(sm + 125952);
    float* sLinv = (float*)(sm + 126464);

    const int tid = threadIdx.x;
    const int wid = tid >> 5, lane = tid & 31;
    const int qb = blockIdx.x * 128;
    const int h = blockIdx.y, b = blockIdx.z;
    const size_t base = ((size_t)(b * NH + h)) * SEQ * HD;
    const float* Qg = g_q + base;
    const float* Kg = g_k + base;
    const float* Vg = g_v + base;

    const int wrow = (wid & 3) * 32;
    const int wcol = (wid >> 2) * 32;
    const int g = lane >> 2, tig = lane & 3;

    // ---- Stage Q once: [128 q][64 d] -> hi/lo, stride 72 ----
#pragma unroll
    for (int it = 0; it < 8; ++it) {
        int id = it * 256 + tid;           // 0..2047
        int row = id >> 4, c = id & 15;    // d = c*4
        float4 v = *reinterpret_cast<const float4*>(
            &Qg[(size_t)(qb + row) * HD + c * 4]);
        __nv_bfloat162 h0, l0, h1, l1;
        split2(v.x, v.y, h0, l0);
        split2(v.z, v.w, h1, l1);
        *reinterpret_cast<__nv_bfloat162*>(&sQh[row * 72 + c * 4]) = h0;
        *reinterpret_cast<__nv_bfloat162*>(&sQh[row * 72 + c * 4 + 2]) = h1;
        *reinterpret_cast<__nv_bfloat162*>(&sQl[row * 72 + c * 4]) = l0;
        *reinterpret_cast<__nv_bfloat162*>(&sQl[row * 72 + c * 4 + 2]) = l1;
    }

    float oacc[2][4][4];
#pragma unroll
    for (int mi = 0; mi < 2; ++mi)
#pragma unroll
        for (int ni = 0; ni < 4; ++ni)
#pragma unroll
            for (int r = 0; r < 4; ++r) oacc[mi][ni][r] = 0.f;
    float m_run = -1e30f, l_run = 0.f;   // meaningful for tid < 128

    for (int kt = 0; kt < SEQ; kt += 64) {
        // ---- Stage K tile [64 kv][64 d] row-major -> hi/lo ----
#pragma unroll
        for (int it = 0; it < 4; ++it) {
            int id = it * 256 + tid;       // 0..1023
            int j = id >> 4, c = id & 15;
            float4 v = *reinterpret_cast<const float4*>(
                &Kg[(size_t)(kt + j) * HD + c * 4]);
            __nv_bfloat162 h0, l0, h1, l1;
            split2(v.x, v.y, h0, l0);
            split2(v.z, v.w, h1, l1);
            *reinterpret_cast<__nv_bfloat162*>(&sKVh[j * 72 + c * 4]) = h0;
            *reinterpret_cast<__nv_bfloat162*>(&sKVh[j * 72 + c * 4 + 2]) = h1;
            *reinterpret_cast<__nv_bfloat162*>(&sKVl[j * 72 + c * 4]) = l0;
            *reinterpret_cast<__nv_bfloat162*>(&sKVl[j * 72 + c * 4 + 2]) = l1;
        }
        __syncthreads();

        // ---- S = Q K^T (128 x 64), 3-term HMMA ----
        float sacc[2][4][4];
#pragma unroll
        for (int mi = 0; mi < 2; ++mi)
#pragma unroll
            for (int ni = 0; ni < 4; ++ni)
#pragma unroll
                for (int r = 0; r < 4; ++r) sacc[mi][ni][r] = 0.f;

#pragma unroll
        for (int ks = 0; ks < 4; ++ks) {
            const int ko = ks * 16;
            uint32_t ah[2][4], al[2][4];
#pragma unroll
            for (int mi = 0; mi < 2; ++mi) {
                const bf16* p = sQh + (wrow + mi * 16 + g) * 72 + ko + 2 * tig;
                ah[mi][0] = *reinterpret_cast<const uint32_t*>(p);
                ah[mi][1] = *reinterpret_cast<const uint32_t*>(p + 8 * 72);
                ah[mi][2] = *reinterpret_cast<const uint32_t*>(p + 8);
                ah[mi][3] = *reinterpret_cast<const uint32_t*>(p + 8 * 72 + 8);
                const bf16* q = sQl + (wrow + mi * 16 + g) * 72 + ko + 2 * tig;
                al[mi][0] = *reinterpret_cast<const uint32_t*>(q);
                al[mi][1] = *reinterpret_cast<const uint32_t*>(q + 8 * 72);
                al[mi][2] = *reinterpret_cast<const uint32_t*>(q + 8);
                al[mi][3] = *reinterpret_cast<const uint32_t*>(q + 8 * 72 + 8);
            }
            uint32_t bhf[4][2], blf[4][2];
#pragma unroll
            for (int ni = 0; ni < 4; ++ni) {
                const bf16* p = sKVh + (wcol + ni * 8 + g) * 72 + ko + 2 * tig;
                bhf[ni][0] = *reinterpret_cast<const uint32_t*>(p);
                bhf[ni][1] = *reinterpret_cast<const uint32_t*>(p + 8);
                const bf16* q = sKVl + (wcol + ni * 8 + g) * 72 + ko + 2 * tig;
                blf[ni][0] = *reinterpret_cast<const uint32_t*>(q);
                blf[ni][1] = *reinterpret_cast<const uint32_t*>(q + 8);
            }
#pragma unroll
            for (int mi = 0; mi < 2; ++mi)
#pragma unroll
                for (int ni = 0; ni < 4; ++ni) {
                    mma16816(sacc[mi][ni], ah[mi], bhf[ni]);
                    mma16816(sacc[mi][ni], ah[mi], blf[ni]);
                    mma16816(sacc[mi][ni], al[mi], bhf[ni]);
                }
        }

        // ---- S^T -> sPt[kv][132] fp32 ----
#pragma unroll
        for (int mi = 0; mi < 2; ++mi)
#pragma unroll
            for (int ni = 0; ni < 4; ++ni) {
                int col = wcol + ni * 8 + 2 * tig;
                int row = wrow + mi * 16 + g;
                sPt[col * 132 + row] = sacc[mi][ni][0];
                sPt[(col + 1) * 132 + row] = sacc[mi][ni][1];
                sPt[col * 132 + row + 8] = sacc[mi][ni][2];
                sPt[(col + 1) * 132 + row + 8] = sacc[mi][ni][3];
            }
        __syncthreads();

        // ---- warps 0-3: softmax row tid; warps 4-7: stage V^T ----
        if (tid < 128) {
            float tmax = -1e30f;
#pragma unroll 16
            for (int j = 0; j < 64; ++j)
                tmax = fmaxf(tmax, sPt[j * 132 + tid]);
            float m_new = fmaxf(m_run, tmax * ATTN_SCALE);
            float a = __expf(m_run - m_new);
            float sum = 0.f;
#pragma unroll 8
            for (int j2 = 0; j2 < 32; ++j2) {
                float p0 = __expf(fmaf(sPt[(2 * j2) * 132 + tid], ATTN_SCALE, -m_new));
                float p1 = __expf(fmaf(sPt[(2 * j2 + 1) * 132 + tid], ATTN_SCALE, -m_new));
                sum += p0 + p1;
                __nv_bfloat162 hh, ll;
                split2(p0, p1, hh, ll);
                sPh[tid * 36 + j2] = *reinterpret_cast<uint32_t*>(&hh);
                sPl[tid * 36 + j2] = *reinterpret_cast<uint32_t*>(&ll);
            }
            l_run = fmaf(l_run, a, sum);
            m_run = m_new;
            sAlpha[tid] = a;
        } else {
            int t2 = tid - 128;
#pragma unroll
            for (int it = 0; it < 8; ++it) {
                int id = it * 128 + t2;        // 0..1023
                int j = id >> 4, c = id & 15;  // kv row j, d = c*4
                float4 v = *reinterpret_cast<const float4*>(
                    &Vg[(size_t)(kt + j) * HD + c * 4]);
                int d = c * 4;
                bf16 h0 = __float2bfloat16(v.x), h1 = __float2bfloat16(v.y);
                bf16 h2 = __float2bfloat16(v.z), h3 = __float2bfloat16(v.w);
                sKVh[(d + 0) * 72 + j] = h0;
                sKVh[(d + 1) * 72 + j] = h1;
                sKVh[(d + 2) * 72 + j] = h2;
                sKVh[(d + 3) * 72 + j] = h3;
                sKVl[(d + 0) * 72 + j] = __float2bfloat16(v.x - __bfloat162float(h0));
                sKVl[(d + 1) * 72 + j] = __float2bfloat16(v.y - __bfloat162float(h1));
                sKVl[(d + 2) * 72 + j] = __float2bfloat16(v.z - __bfloat162float(h2));
                sKVl[(d + 3) * 72 + j] = __float2bfloat16(v.w - __bfloat162float(h3));
            }
        }
        __syncthreads();

        // ---- rescale O by alpha ----
        {
            float a0 = sAlpha[wrow + g];
            float a1 = sAlpha[wrow + g + 8];
            float a2 = sAlpha[wrow + g + 16];
            float a3 = sAlpha[wrow + g + 24];
#pragma unroll
            for (int ni = 0; ni < 4; ++ni) {
                oacc[0][ni][0] *= a0; oacc[0][ni][1] *= a0;
                oacc[0][ni][2] *= a1; oacc[0][ni][3] *= a1;
                oacc[1][ni][0] *= a2; oacc[1][ni][1] *= a2;
                oacc[1][ni][2] *= a3; oacc[1][ni][3] *= a3;
            }
        }

        // ---- O += P V  (A = P [q][kv] packed u32, B = V^T [d][kv]) ----
#pragma unroll
        for (int ks = 0; ks < 4; ++ks) {
            uint32_t pah[2][4], pal[2][4];
#pragma unroll
            for (int mi = 0; mi < 2; ++mi) {
                int bidx = (wrow + mi * 16 + g) * 36 + ks * 8 + tig;
                pah[mi][0] = sPh[bidx];
                pah[mi][1] = sPh[bidx + 8 * 36];
                pah[mi][2] = sPh[bidx + 4];
                pah[mi][3] = sPh[bidx + 8 * 36 + 4];
                pal[mi][0] = sPl[bidx];
                pal[mi][1] = sPl[bidx + 8 * 36];
                pal[mi][2] = sPl[bidx + 4];
                pal[mi][3] = sPl[bidx + 8 * 36 + 4];
            }
            uint32_t vbh[4][2], vbl[4][2];
#pragma unroll
            for (int ni = 0; ni < 4; ++ni) {
                const bf16* p = sKVh + (wcol + ni * 8 + g) * 72 + ks * 16 + 2 * tig;
                vbh[ni][0] = *reinterpret_cast<const uint32_t*>(p);
                vbh[ni][1] = *reinterpret_cast<const uint32_t*>(p + 8);
                const bf16* q = sKVl + (wcol + ni * 8 + g) * 72 + ks * 16 + 2 * tig;
                vbl[ni][0] = *reinterpret_cast<const uint32_t*>(q);
                vbl[ni][1] = *reinterpret_cast<const uint32_t*>(q + 8);
            }
#pragma unroll
            for (int mi = 0; mi < 2; ++mi)
#pragma unroll
                for (int ni = 0; ni < 4; ++ni) {
                    mma16816(oacc[mi][ni], pah[mi], vbh[ni]);
                    mma16816(oacc[mi][ni], pah[mi], vbl[ni]);
                    mma16816(oacc[mi][ni], pal[mi], vbh[ni]);
                }
        }
        __syncthreads();
    }

    if (tid < 128) sLinv[tid] = 1.f / l_run;
    __syncthreads();

    float* Og = g_ctx + base;
#pragma unroll
    for (int mi = 0; mi < 2; ++mi) {
        int r0 = wrow + mi * 16 + g;
        float inv0 = sLinv[r0], inv1 = sLinv[r0 + 8];
#pragma unroll
        for (int ni = 0; ni < 4; ++ni) {
            int col = wcol + ni * 8 + 2 * tig;
            *reinterpret_cast<float2*>(&Og[(size_t)(qb + r0) * HD + col]) =
                make_float2(oacc[mi][ni][0] * inv0, oacc[mi][ni][1] * inv0);
            *reinterpret_cast<float2*>(&Og[(size_t)(qb + r0 + 8) * HD + col]) =
                make_float2(oacc[mi][ni][2] * inv1, oacc[mi][ni][3] * inv1);
        }
    }
}

// ---------------------------------------------------------------------------
// Proj GEMM (byte-identical to R2/R7 passing kernel)
// ---------------------------------------------------------------------------
__global__ __launch_bounds__(256) void proj_gemm_kernel(
    const float* __restrict__ W, const float* __restrict__ bias,
    float* __restrict__ out)
{
    __shared__ float Ats[16 * 128];
    __shared__ float Bs[16 * 128];

    const int tid = threadIdx.x;
    const int nb = blockIdx.x * 128;
    const int mb = blockIdx.y * 128;

    const int warp = tid >> 5, lane = tid & 31;
    const int wm = warp & 3, wn = warp >> 2;
    const int lm = lane & 3, ln = lane >> 2;
    const int ri = wm * 32 + lm * 8;
    const int cj = wn * 64 + ln * 8;

    float acc[8][8];
#pragma unroll
    for (int r = 0; r < 8; ++r)
#pragma unroll
        for (int c = 0; c < 8; ++c) acc[r][c] = 0.f;

    for (int kt = 0; kt < DMODEL; kt += 16) {
        const int hk = kt >> 6;
        const int dk = kt & 63;
#pragma unroll
        for (int it = 0; it < 2; ++it) {
            int g = it * 256 + tid;
            int row = g >> 2, k4 = (g & 3) << 2;
            int m = mb + row;
            int b = m >> 10, s = m & 1023;
            float4 v = *reinterpret_cast<const float4*>(
                &g_ctx[(((size_t)(b * NH + hk) * SEQ + s) * HD) + dk + k4]);
            Ats[(k4 + 0) * 128 + row] = v.x;
            Ats[(k4 + 1) * 128 + row] = v.y;
            Ats[(k4 + 2) * 128 + row] = v.z;
            Ats[(k4 + 3) * 128 + row] = v.w;
        }
#pragma unroll
        for (int it = 0; it < 2; ++it) {
            int g = it * 256 + tid;
            int k = g >> 5, n4 = (g & 31) << 2;
            *reinterpret_cast<float4*>(&Bs[k * 128 + n4]) =
                *reinterpret_cast<const float4*>(
                    &W[(size_t)(kt + k) * DMODEL + nb + n4]);
        }
        __syncthreads();
#pragma unroll
        for (int k = 0; k < 16; ++k) {
            float a[8], b[8];
            *reinterpret_cast<float4*>(&a[0]) =
                *reinterpret_cast<const float4*>(&Ats[k * 128 + ri]);
            *reinterpret_cast<float4*>(&a[4]) =
                *reinterpret_cast<const float4*>(&Ats[k * 128 + ri + 4]);
            *reinterpret_cast<float4*>(&b[0]) =
                *reinterpret_cast<const float4*>(&Bs[k * 128 + cj]);
            *reinterpret_cast<float4*>(&b[4]) =
                *reinterpret_cast<const float4*>(&Bs[k * 128 + cj + 4]);
#pragma unroll
            for (int r = 0; r < 8; ++r)
#pragma unroll
                for (int c = 0; c < 8; ++c)
                    acc[r][c] = fmaf(a[r], b[c], acc[r][c]);
        }
        __syncthreads();
    }

    float bb[8];
#pragma unroll
    for (int c = 0; c < 8; ++c) bb[c] = bias[nb + cj + c];
#pragma unroll
    for (int r = 0; r < 8; ++r) {
        int m = mb + ri + r;
        float* p = out + (size_t)m * DMODEL + nb + cj;
        *reinterpret_cast<float4*>(p) = make_float4(
            acc[r][0] + bb[0], acc[r][1] + bb[1],
            acc[r][2] + bb[2], acc[r][3] + bb[3]);
        *reinterpret_cast<float4*>(p + 4) = make_float4(
            acc[r][4] + bb[4], acc[r][5] + bb[5],
            acc[r][6] + bb[6], acc[r][7] + bb[7]);
    }
}

// ---------------------------------------------------------------------------
extern "C" void kernel_launch(void* const* d_in, const int* in_sizes, int n_in,
                              void* d_out, int out_size)
{
    const float* hidden = (const float*)d_in[0];
    const float* w_qkv  = (const float*)d_in[1];
    const float* b_qkv  = (const float*)d_in[2];
    const float* w_proj = (const float*)d_in[3];
    const float* b_proj = (const float*)d_in[4];
    float* out = (float*)d_out;

    cudaFuncSetAttribute(attn_hmma,
                         cudaFuncAttributeMaxDynamicSharedMemorySize,
                         ATTN_SMEM);

    qkv_gemm_hmma<<<dim3(NQKV / 128, MTOT / 128), 256>>>(hidden, w_qkv, b_qkv);
    attn_hmma<<<dim3(SEQ / 128, NH, BATCH), 256, ATTN_SMEM>>>();
    proj_gemm_kernel<<<dim3(DMODEL / 128, MTOT / 128), 256>>>(
        w_proj, b_proj, out);
}